// round 5
// baseline (speedup 1.0000x reference)
#include <cuda_runtime.h>

#define R 128
#define PROBE_BYTES (6 * R * R * 3 * 4)   // 1179648, ≡ 0 mod 16
#define FACE_BYTES  (R * R * 3 * 4)       // 196608,  ≡ 0 mod 16

__global__ __launch_bounds__(256) void multienv_kernel(
    const float* __restrict__ xyz,
    const float* __restrict__ l,
    const float* __restrict__ base,
    float* __restrict__ out,
    int n)
{
    int i = blockIdx.x * blockDim.x + threadIdx.x;
    if (i >= n) return;

    // ---- direction normalize ----
    float lx = l[3 * i + 0], ly = l[3 * i + 1], lz = l[3 * i + 2];
    float dot = lx * lx + ly * ly + lz * lz;
    float inv = rsqrtf(fmaxf(dot, 1e-18f));
    float dx = lx * inv, dy = ly * inv, dz = lz * inv;

    // ---- cube face / uv (OpenGL convention) ----
    float ax = fabsf(dx), ay = fabsf(dy), az = fabsf(dz);
    bool is_x = (ax >= ay) && (ax >= az);
    bool is_y = (!is_x) && (ay >= az);
    int face;
    float ma, sc, tc;
    if (is_x) {
        face = (dx >= 0.0f) ? 0 : 1;
        ma = ax;
        sc = (dx >= 0.0f) ? -dz : dz;
        tc = -dy;
    } else if (is_y) {
        face = (dy >= 0.0f) ? 2 : 3;
        ma = ay;
        sc = dx;
        tc = (dy >= 0.0f) ? dz : -dz;
    } else {
        face = (dz >= 0.0f) ? 4 : 5;
        ma = az;
        sc = (dz >= 0.0f) ? dx : -dx;
        tc = -dy;
    }
    ma = fmaxf(ma, 1e-9f);
    float rma = __fdividef(1.0f, ma);
    float u = 0.5f * (sc * rma + 1.0f);
    float v = 0.5f * (tc * rma + 1.0f);

    // ---- bilinear texel coords ----
    float fx = u * (float)R - 0.5f;
    float fy = v * (float)R - 0.5f;
    float x0f = floorf(fx), y0f = floorf(fy);
    float tx = fx - x0f, ty = fy - y0f;
    int x0 = min(max((int)x0f, 0), R - 1);
    int x1 = min(max((int)x0f + 1, 0), R - 1);
    int y0 = min(max((int)y0f, 0), R - 1);
    int y1 = min(max((int)y0f + 1, 0), R - 1);

    // chunk starts at texel cs covering texels cs, cs+1 (6 floats, 24 bytes)
    int cs   = min(x0, R - 2);
    int off0 = x0 - cs;            // 0 or 1
    int off1 = x1 - cs;            // 0 or 1
    float gx0 = (off0 ? 0.0f : (1.0f - tx)) + (off1 ? 0.0f : tx);
    float gx1 = 1.0f - gx0;

    // byte offsets of the two row-chunks within a probe
    unsigned rb0 = (unsigned)face * FACE_BYTES + (unsigned)(y0 * R + cs) * 12u;
    unsigned rb1 = (unsigned)face * FACE_BYTES + (unsigned)(y1 * R + cs) * 12u;

    // misalignment phase: identical for all 16 chunks of this query
    int k = (int)((rb0 & 15u) >> 2);   // 0..3
    bool k1 = (k == 1), k2 = (k == 2), k3 = (k == 3);

    // ---- trilinear probe corners; GRID_RES = (8,8,4) ----
    float px = xyz[3 * i + 0], py = xyz[3 * i + 1], pz = xyz[3 * i + 2];
    float cx = fminf(fmaxf(px * 7.0f, 0.0f), 7.0f);
    float cy = fminf(fmaxf(py * 7.0f, 0.0f), 7.0f);
    float cz = fminf(fmaxf(pz * 3.0f, 0.0f), 3.0f);
    int ix0 = (int)floorf(cx);
    int iy0 = (int)floorf(cy);
    int iz0 = (int)floorf(cz);
    int ix1 = min(ix0 + 1, 7);
    int iy1 = min(iy0 + 1, 7);
    int iz1 = min(iz0 + 1, 3);
    float gx = cx - (float)ix0;
    float gy = cy - (float)iy0;
    float gz = cz - (float)iz0;

    unsigned pbyte[8];
    float pw[8];
    {
        float wx0 = 1.0f - gx, wx1 = gx;
        float wy0 = 1.0f - gy, wy1 = gy;
        float wz0 = 1.0f - gz, wz1 = gz;
        unsigned bx0 = (unsigned)ix0 * 32u, bx1 = (unsigned)ix1 * 32u;
        unsigned by0 = (unsigned)iy0 * 4u,  by1 = (unsigned)iy1 * 4u;
        pbyte[0] = (bx0 + by0 + iz0) * (unsigned)PROBE_BYTES;  pw[0] = wx0 * wy0 * wz0;
        pbyte[1] = (bx0 + by0 + iz1) * (unsigned)PROBE_BYTES;  pw[1] = wx0 * wy0 * wz1;
        pbyte[2] = (bx0 + by1 + iz0) * (unsigned)PROBE_BYTES;  pw[2] = wx0 * wy1 * wz0;
        pbyte[3] = (bx0 + by1 + iz1) * (unsigned)PROBE_BYTES;  pw[3] = wx0 * wy1 * wz1;
        pbyte[4] = (bx1 + by0 + iz0) * (unsigned)PROBE_BYTES;  pw[4] = wx1 * wy0 * wz0;
        pbyte[5] = (bx1 + by0 + iz1) * (unsigned)PROBE_BYTES;  pw[5] = wx1 * wy0 * wz1;
        pbyte[6] = (bx1 + by1 + iz0) * (unsigned)PROBE_BYTES;  pw[6] = wx1 * wy1 * wz0;
        pbyte[7] = (bx1 + by1 + iz1) * (unsigned)PROBE_BYTES;  pw[7] = wx1 * wy1 * wz1;
    }
    float wsum = pw[0] + pw[1] + pw[2] + pw[3] + pw[4] + pw[5] + pw[6] + pw[7];
    float wscale = __fdividef(1.0f, fmaxf(wsum, 1e-8f));

    float wty0 = 1.0f - ty, wty1 = ty;

    const char* basec = (const char*)base;

    float acc0 = 0.0f, acc1 = 0.0f, acc2 = 0.0f;

    // 16 chunks processed as 4 batches of 4 — loads of a batch are issued
    // back-to-back before any extraction, maximizing outstanding requests.
#pragma unroll
    for (int half = 0; half < 4; half++) {
        const int r   = half >> 1;         // 0,0,1,1
        const int pb0 = (half & 1) * 4;    // 0,4,0,4
        unsigned rb = r ? rb1 : rb0;
        float    wy = r ? wty1 : wty0;

        float4 A[4], B[4];
        float  E[4];
#pragma unroll
        for (int j = 0; j < 4; j++) {
            unsigned f = (pbyte[pb0 + j] + rb) & ~15u;
            A[j] = __ldcg((const float4*)(basec + f));
            B[j] = __ldcg((const float4*)(basec + f + 16));
            E[j] = 0.0f;
            if (k3) E[j] = __ldcg((const float*)(basec + f + 32));
        }
#pragma unroll
        for (int j = 0; j < 4; j++) {
            float4 Aj = A[j], Bj = B[j];
            float  Ej = E[j];
            // c_m = elems[k + m], elems = {A.x..A.w, B.x..B.w, E}
            float c0 = k1 ? Aj.y : Aj.x;  c0 = k2 ? Aj.z : c0;  c0 = k3 ? Aj.w : c0;
            float c1 = k1 ? Aj.z : Aj.y;  c1 = k2 ? Aj.w : c1;  c1 = k3 ? Bj.x : c1;
            float c2 = k1 ? Aj.w : Aj.z;  c2 = k2 ? Bj.x : c2;  c2 = k3 ? Bj.y : c2;
            float c3 = k1 ? Bj.x : Aj.w;  c3 = k2 ? Bj.y : c3;  c3 = k3 ? Bj.z : c3;
            float c4 = k1 ? Bj.y : Bj.x;  c4 = k2 ? Bj.z : c4;  c4 = k3 ? Bj.w : c4;
            float c5 = k1 ? Bj.z : Bj.y;  c5 = k2 ? Bj.w : c5;  c5 = k3 ? Ej   : c5;

            float w = pw[pb0 + j] * wy;
            acc0 = fmaf(w, fmaf(gx0, c0, gx1 * c3), acc0);
            acc1 = fmaf(w, fmaf(gx0, c1, gx1 * c4), acc1);
            acc2 = fmaf(w, fmaf(gx0, c2, gx1 * c5), acc2);
        }
    }
    acc0 *= wscale; acc1 *= wscale; acc2 *= wscale;

    // sigmoid(x) * 10
    out[3 * i + 0] = __fdividef(10.0f, 1.0f + __expf(-acc0));
    out[3 * i + 1] = __fdividef(10.0f, 1.0f + __expf(-acc1));
    out[3 * i + 2] = __fdividef(10.0f, 1.0f + __expf(-acc2));
}

extern "C" void kernel_launch(void* const* d_in, const int* in_sizes, int n_in,
                              void* d_out, int out_size) {
    const float* xyz  = (const float*)d_in[0];
    const float* l    = (const float*)d_in[1];
    const float* base = (const float*)d_in[2];
    float* out = (float*)d_out;
    int n = in_sizes[0] / 3;   // 524288
    int threads = 256;
    int blocks = (n + threads - 1) / threads;
    multienv_kernel<<<blocks, threads>>>(xyz, l, base, out, n);
}

// round 6
// speedup vs baseline: 1.2991x; 1.2991x over previous
#include <cuda_runtime.h>

#define R 128
#define PROBE_BYTES (6 * R * R * 3 * 4)   // 1179648, ≡ 0 mod 16
#define FACE_BYTES  (R * R * 3 * 4)       // 196608,  ≡ 0 mod 16

__global__ __launch_bounds__(256) void multienv_kernel(
    const float* __restrict__ xyz,
    const float* __restrict__ l,
    const float* __restrict__ base,
    float* __restrict__ out,
    int n)
{
    int i = blockIdx.x * blockDim.x + threadIdx.x;
    if (i >= n) return;

    // ---- direction normalize ----
    float lx = l[3 * i + 0], ly = l[3 * i + 1], lz = l[3 * i + 2];
    float dot = lx * lx + ly * ly + lz * lz;
    float inv = rsqrtf(fmaxf(dot, 1e-18f));
    float dx = lx * inv, dy = ly * inv, dz = lz * inv;

    // ---- cube face / uv (OpenGL convention) ----
    float ax = fabsf(dx), ay = fabsf(dy), az = fabsf(dz);
    bool is_x = (ax >= ay) && (ax >= az);
    bool is_y = (!is_x) && (ay >= az);
    int face;
    float ma, sc, tc;
    if (is_x) {
        face = (dx >= 0.0f) ? 0 : 1;
        ma = ax;
        sc = (dx >= 0.0f) ? -dz : dz;
        tc = -dy;
    } else if (is_y) {
        face = (dy >= 0.0f) ? 2 : 3;
        ma = ay;
        sc = dx;
        tc = (dy >= 0.0f) ? dz : -dz;
    } else {
        face = (dz >= 0.0f) ? 4 : 5;
        ma = az;
        sc = (dz >= 0.0f) ? dx : -dx;
        tc = -dy;
    }
    ma = fmaxf(ma, 1e-9f);
    float rma = __fdividef(1.0f, ma);
    float u = 0.5f * (sc * rma + 1.0f);
    float v = 0.5f * (tc * rma + 1.0f);

    // ---- bilinear texel coords ----
    float fx = u * (float)R - 0.5f;
    float fy = v * (float)R - 0.5f;
    float x0f = floorf(fx), y0f = floorf(fy);
    float tx = fx - x0f, ty = fy - y0f;
    int x0 = min(max((int)x0f, 0), R - 1);
    int x1 = min(max((int)x0f + 1, 0), R - 1);
    int y0 = min(max((int)y0f, 0), R - 1);
    int y1 = min(max((int)y0f + 1, 0), R - 1);

    // chunk starts at texel cs covering texels cs, cs+1 (6 floats, 24 bytes)
    int cs   = min(x0, R - 2);
    int off0 = x0 - cs;            // 0 or 1
    int off1 = x1 - cs;            // 0 or 1
    // weight applied to texel-at-cs (c0..c2) and texel-at-cs+1 (c3..c5)
    float gx0 = (off0 ? 0.0f : (1.0f - tx)) + (off1 ? 0.0f : tx);
    float gx1 = 1.0f - gx0;

    // byte offsets of the two row-chunks within a probe
    unsigned rb0 = (unsigned)face * FACE_BYTES + (unsigned)(y0 * R + cs) * 12u;
    unsigned rb1 = (unsigned)face * FACE_BYTES + (unsigned)(y1 * R + cs) * 12u;

    // misalignment phase: identical for all 16 chunks of this query
    int k = (int)((rb0 & 15u) >> 2);   // 0..3
    bool k1 = (k == 1), k2 = (k == 2), k3 = (k == 3);

    // ---- trilinear probe corners; GRID_RES = (8,8,4) ----
    float px = xyz[3 * i + 0], py = xyz[3 * i + 1], pz = xyz[3 * i + 2];
    float cx = fminf(fmaxf(px * 7.0f, 0.0f), 7.0f);
    float cy = fminf(fmaxf(py * 7.0f, 0.0f), 7.0f);
    float cz = fminf(fmaxf(pz * 3.0f, 0.0f), 3.0f);
    int ix0 = (int)floorf(cx);
    int iy0 = (int)floorf(cy);
    int iz0 = (int)floorf(cz);
    int ix1 = min(ix0 + 1, 7);
    int iy1 = min(iy0 + 1, 7);
    int iz1 = min(iz0 + 1, 3);
    float gx = cx - (float)ix0;
    float gy = cy - (float)iy0;
    float gz = cz - (float)iz0;

    unsigned pbyte[8];
    float pw[8];
    {
        float wx0 = 1.0f - gx, wx1 = gx;
        float wy0 = 1.0f - gy, wy1 = gy;
        float wz0 = 1.0f - gz, wz1 = gz;
        unsigned bx0 = (unsigned)ix0 * 32u, bx1 = (unsigned)ix1 * 32u;
        unsigned by0 = (unsigned)iy0 * 4u,  by1 = (unsigned)iy1 * 4u;
        pbyte[0] = (bx0 + by0 + iz0) * (unsigned)PROBE_BYTES;  pw[0] = wx0 * wy0 * wz0;
        pbyte[1] = (bx0 + by0 + iz1) * (unsigned)PROBE_BYTES;  pw[1] = wx0 * wy0 * wz1;
        pbyte[2] = (bx0 + by1 + iz0) * (unsigned)PROBE_BYTES;  pw[2] = wx0 * wy1 * wz0;
        pbyte[3] = (bx0 + by1 + iz1) * (unsigned)PROBE_BYTES;  pw[3] = wx0 * wy1 * wz1;
        pbyte[4] = (bx1 + by0 + iz0) * (unsigned)PROBE_BYTES;  pw[4] = wx1 * wy0 * wz0;
        pbyte[5] = (bx1 + by0 + iz1) * (unsigned)PROBE_BYTES;  pw[5] = wx1 * wy0 * wz1;
        pbyte[6] = (bx1 + by1 + iz0) * (unsigned)PROBE_BYTES;  pw[6] = wx1 * wy1 * wz0;
        pbyte[7] = (bx1 + by1 + iz1) * (unsigned)PROBE_BYTES;  pw[7] = wx1 * wy1 * wz1;
    }
    float wsum = pw[0] + pw[1] + pw[2] + pw[3] + pw[4] + pw[5] + pw[6] + pw[7];
    float wscale = __fdividef(1.0f, fmaxf(wsum, 1e-8f));

    float wty0 = 1.0f - ty, wty1 = ty;

    const char* basec = (const char*)base;

    float acc0 = 0.0f, acc1 = 0.0f, acc2 = 0.0f;

#pragma unroll
    for (int p = 0; p < 8; p++) {
        unsigned pb = pbyte[p];
        float wp = pw[p];
#pragma unroll
        for (int r = 0; r < 2; r++) {
            unsigned s = pb + (r ? rb1 : rb0);
            unsigned f = s & ~15u;
            float4 A = __ldg((const float4*)(basec + f));
            float4 B = __ldg((const float4*)(basec + f + 16));
            // tail element: only fetched when k==3 (predicated single-load body;
            // k3 is thread-uniform so no divergence cost, and inactive lanes
            // issue no memory request)
            float E = 0.0f;
            if (k3) E = __ldg((const float*)(basec + f + 32));

            // c_j = elems[k + j], elems = {A.x..A.w, B.x..B.w, E}
            float c0 = k1 ? A.y : A.x;  c0 = k2 ? A.z : c0;  c0 = k3 ? A.w : c0;
            float c1 = k1 ? A.z : A.y;  c1 = k2 ? A.w : c1;  c1 = k3 ? B.x : c1;
            float c2 = k1 ? A.w : A.z;  c2 = k2 ? B.x : c2;  c2 = k3 ? B.y : c2;
            float c3 = k1 ? B.x : A.w;  c3 = k2 ? B.y : c3;  c3 = k3 ? B.z : c3;
            float c4 = k1 ? B.y : B.x;  c4 = k2 ? B.z : c4;  c4 = k3 ? B.w : c4;
            float c5 = k1 ? B.z : B.y;  c5 = k2 ? B.w : c5;  c5 = k3 ? E   : c5;

            float w = wp * (r ? wty1 : wty0);
            acc0 = fmaf(w, fmaf(gx0, c0, gx1 * c3), acc0);
            acc1 = fmaf(w, fmaf(gx0, c1, gx1 * c4), acc1);
            acc2 = fmaf(w, fmaf(gx0, c2, gx1 * c5), acc2);
        }
    }
    acc0 *= wscale; acc1 *= wscale; acc2 *= wscale;

    // sigmoid(x) * 10
    out[3 * i + 0] = __fdividef(10.0f, 1.0f + __expf(-acc0));
    out[3 * i + 1] = __fdividef(10.0f, 1.0f + __expf(-acc1));
    out[3 * i + 2] = __fdividef(10.0f, 1.0f + __expf(-acc2));
}

extern "C" void kernel_launch(void* const* d_in, const int* in_sizes, int n_in,
                              void* d_out, int out_size) {
    const float* xyz  = (const float*)d_in[0];
    const float* l    = (const float*)d_in[1];
    const float* base = (const float*)d_in[2];
    float* out = (float*)d_out;
    int n = in_sizes[0] / 3;   // 524288
    int threads = 256;
    int blocks = (n + threads - 1) / threads;
    multienv_kernel<<<blocks, threads>>>(xyz, l, base, out, n);
}